// round 3
// baseline (speedup 1.0000x reference)
#include <cuda_runtime.h>
#include <cuda_bf16.h>

#define NSAMP 128

__global__ __launch_bounds__(NSAMP) void surf_kernel(
    const int2*   __restrict__ x,       // [B, N] pairs of int32 grid indices
    const float*  __restrict__ dvec,    // [B, 16]
    const float4* __restrict__ grid,    // [TABLE] float4 (FEAT=4)
    const float*  __restrict__ W0,      // [22, 8] row-major
    const float*  __restrict__ W1,      // [8, 3]  row-major
    float*        __restrict__ out_sigma, // [B, N]
    float*        __restrict__ out_rgb)   // [B, 3]
{
    const int b0   = blockIdx.x * 2;    // two rays per block
    const int b1   = b0 + 1;
    const int n    = threadIdx.x;
    const int lane = n & 31;
    const int wid  = n >> 5;

    // ---- issue ALL long-latency loads first: 2 idx loads, then 4 gathers ----
    const int2 idxA = __ldcs(&x[(long)b0 * NSAMP + n]);
    const int2 idxB = __ldcs(&x[(long)b1 * NSAMP + n]);
    const float4 f0A = __ldg(&grid[idxA.x]);
    const float4 f1A = __ldg(&grid[idxA.y]);
    const float4 f0B = __ldg(&grid[idxB.x]);
    const float4 f1B = __ldg(&grid[idxB.y]);

    __shared__ float sW0g[6][8];     // W0 rows 16..21 (geo-feat part)
    __shared__ float sW1[8][3];
    __shared__ float sBase[2][8];    // per-ray d @ W0[0:16]
    __shared__ float sD[2][16];
    __shared__ float sWarpProd[2][4];
    __shared__ float sRGB[2][4][3];

    // ---- cooperative constant loads (under gather shadow) ----
    if (n < 48) {
        int r = n >> 3, c = n & 7;
        sW0g[r][c] = W0[(16 + r) * 8 + c];
    } else if (n < 72) {
        int t = n - 48;
        sW1[t / 3][t % 3] = W1[t];
    } else if (n < 104) {
        int t = n - 72;                    // 0..31 : two rays x 16 dims
        sD[t >> 4][t & 15] = dvec[(t >> 4 ? b1 : b0) * 16 + (t & 15)];
    }
    __syncthreads();

    // per-ray hidden bias from view direction (16 threads: 2 rays x 8 cols)
    if (n < 16) {
        int r = n >> 3, j = n & 7;
        float acc = 0.f;
        #pragma unroll
        for (int i = 0; i < 16; i++) acc = fmaf(sD[r][i], W0[i * 8 + j], acc);
        sBase[r][j] = acc;
    }

    const float sigA = 1.0f / (1.0f + __expf(-(f0A.x * f1A.x)));
    const float sigB = 1.0f / (1.0f + __expf(-(f0B.x * f1B.x)));
    __stcs(&out_sigma[(long)b0 * NSAMP + n], sigA);
    __stcs(&out_sigma[(long)b1 * NSAMP + n], sigB);

    __syncthreads();   // sBase ready

    // ---- tiny MLP per ray: 6 -> 8 relu -> 3 sigmoid ----
    float colA[3], colB[3];
    {
        float h[8];
        #pragma unroll
        for (int j = 0; j < 8; j++) {
            float v = sBase[0][j];
            v = fmaf(f0A.y, sW0g[0][j], v);
            v = fmaf(f0A.z, sW0g[1][j], v);
            v = fmaf(f0A.w, sW0g[2][j], v);
            v = fmaf(f1A.y, sW0g[3][j], v);
            v = fmaf(f1A.z, sW0g[4][j], v);
            v = fmaf(f1A.w, sW0g[5][j], v);
            h[j] = fmaxf(v, 0.f);
        }
        #pragma unroll
        for (int c = 0; c < 3; c++) {
            float v = 0.f;
            #pragma unroll
            for (int j = 0; j < 8; j++) v = fmaf(h[j], sW1[j][c], v);
            colA[c] = 1.0f / (1.0f + __expf(-v));
        }
    }
    {
        float h[8];
        #pragma unroll
        for (int j = 0; j < 8; j++) {
            float v = sBase[1][j];
            v = fmaf(f0B.y, sW0g[0][j], v);
            v = fmaf(f0B.z, sW0g[1][j], v);
            v = fmaf(f0B.w, sW0g[2][j], v);
            v = fmaf(f1B.y, sW0g[3][j], v);
            v = fmaf(f1B.z, sW0g[4][j], v);
            v = fmaf(f1B.w, sW0g[5][j], v);
            h[j] = fmaxf(v, 0.f);
        }
        #pragma unroll
        for (int c = 0; c < 3; c++) {
            float v = 0.f;
            #pragma unroll
            for (int j = 0; j < 8; j++) v = fmaf(h[j], sW1[j][c], v);
            colB[c] = 1.0f / (1.0f + __expf(-v));
        }
    }

    // ---- exclusive product-scans for transmittance (both rays) ----
    float spA = 1.0f - sigA;
    float spB = 1.0f - sigB;
    #pragma unroll
    for (int o = 1; o < 32; o <<= 1) {
        float vA = __shfl_up_sync(0xffffffffu, spA, o);
        float vB = __shfl_up_sync(0xffffffffu, spB, o);
        if (lane >= o) { spA *= vA; spB *= vB; }
    }
    if (lane == 31) { sWarpProd[0][wid] = spA; sWarpProd[1][wid] = spB; }
    __syncthreads();
    float preA = 1.0f, preB = 1.0f;
    #pragma unroll
    for (int w = 0; w < 4; w++) if (w < wid) { preA *= sWarpProd[0][w]; preB *= sWarpProd[1][w]; }
    float exA = __shfl_up_sync(0xffffffffu, spA, 1);
    float exB = __shfl_up_sync(0xffffffffu, spB, 1);
    if (lane == 0) { exA = 1.0f; exB = 1.0f; }
    const float wgtA = preA * exA * sigA;
    const float wgtB = preB * exB * sigB;

    // ---- rgb = sum_n wgt * color (both rays) ----
    float a0 = wgtA * colA[0], a1 = wgtA * colA[1], a2 = wgtA * colA[2];
    float q0 = wgtB * colB[0], q1 = wgtB * colB[1], q2 = wgtB * colB[2];
    #pragma unroll
    for (int o = 16; o > 0; o >>= 1) {
        a0 += __shfl_down_sync(0xffffffffu, a0, o);
        a1 += __shfl_down_sync(0xffffffffu, a1, o);
        a2 += __shfl_down_sync(0xffffffffu, a2, o);
        q0 += __shfl_down_sync(0xffffffffu, q0, o);
        q1 += __shfl_down_sync(0xffffffffu, q1, o);
        q2 += __shfl_down_sync(0xffffffffu, q2, o);
    }
    if (lane == 0) {
        sRGB[0][wid][0] = a0; sRGB[0][wid][1] = a1; sRGB[0][wid][2] = a2;
        sRGB[1][wid][0] = q0; sRGB[1][wid][1] = q1; sRGB[1][wid][2] = q2;
    }
    __syncthreads();
    if (n < 6) {
        int r = n / 3, c = n % 3;
        out_rgb[(r ? b1 : b0) * 3 + c] =
            sRGB[r][0][c] + sRGB[r][1][c] + sRGB[r][2][c] + sRGB[r][3][c];
    }
}

extern "C" void kernel_launch(void* const* d_in, const int* in_sizes, int n_in,
                              void* d_out, int out_size) {
    const int2*   x    = (const int2*)d_in[0];
    const float*  dvec = (const float*)d_in[1];
    const float4* grid = (const float4*)d_in[2];
    const float*  W0   = (const float*)d_in[3];
    const float*  W1   = (const float*)d_in[4];

    const int B = in_sizes[1] / 16;          // d is [B, 16]
    float* out_sigma = (float*)d_out;        // [B, 128]
    float* out_rgb   = out_sigma + (long)B * NSAMP;  // [B, 3]

    surf_kernel<<<B / 2, NSAMP>>>(x, dvec, grid, W0, W1, out_sigma, out_rgb);
}

// round 5
// speedup vs baseline: 1.0142x; 1.0142x over previous
#include <cuda_runtime.h>
#include <cuda_bf16.h>

#define NSAMP 128
#define PIN_ENTRIES 7500000   // 120 MB of the 268 MB table kept L2-resident

__device__ __forceinline__ float4 ldg_pol(const float4* p, unsigned long long pol) {
    float4 v;
    asm volatile("ld.global.nc.L2::cache_hint.v4.f32 {%0,%1,%2,%3}, [%4], %5;"
                 : "=f"(v.x), "=f"(v.y), "=f"(v.z), "=f"(v.w)
                 : "l"(p), "l"(pol));
    return v;
}

__global__ __launch_bounds__(NSAMP) void surf_kernel(
    const int2*   __restrict__ x,       // [B, N] pairs of int32 grid indices
    const float*  __restrict__ dvec,    // [B, 16]
    const float4* __restrict__ grid,    // [TABLE] float4 (FEAT=4)
    const float*  __restrict__ W0,      // [22, 8] row-major
    const float*  __restrict__ W1,      // [8, 3]  row-major
    float*        __restrict__ out_sigma, // [B, N]
    float*        __restrict__ out_rgb)   // [B, 3]
{
    const int b    = blockIdx.x;
    const int n    = threadIdx.x;
    const int lane = n & 31;
    const int wid  = n >> 5;

    unsigned long long polLast, polFirst;
    asm("createpolicy.fractional.L2::evict_last.b64 %0, 1.0;"  : "=l"(polLast));
    asm("createpolicy.fractional.L2::evict_first.b64 %0, 1.0;" : "=l"(polFirst));

    // ---- issue long-latency gathers FIRST (everything else hides under them) ----
    const int2 idx = __ldcs(&x[(long)b * NSAMP + n]);
    const float4 f0 = ldg_pol(&grid[idx.x], idx.x < PIN_ENTRIES ? polLast : polFirst);
    const float4 f1 = ldg_pol(&grid[idx.y], idx.y < PIN_ENTRIES ? polLast : polFirst);

    __shared__ float sW0g[6][8];   // W0 rows 16..21 (geo-feat part)
    __shared__ float sW1[8][3];
    __shared__ float sBase[8];     // per-ray d @ W0[0:16]
    __shared__ float sD[16];
    __shared__ float sWarpProd[4];
    __shared__ float sRGB[4][3];

    // ---- cooperative constant loads (under gather shadow) ----
    if (n < 48) {
        int r = n >> 3, c = n & 7;
        sW0g[r][c] = W0[(16 + r) * 8 + c];
    } else if (n < 72) {
        int t = n - 48;
        sW1[t / 3][t % 3] = W1[t];
    } else if (n < 88) {
        sD[n - 72] = dvec[b * 16 + (n - 72)];
    }
    __syncthreads();

    // per-ray hidden bias from view direction (amortized over 128 samples)
    if (n < 8) {
        float acc = 0.f;
        #pragma unroll
        for (int i = 0; i < 16; i++) acc = fmaf(sD[i], W0[i * 8 + n], acc);
        sBase[n] = acc;
    }

    const float sigma = 1.0f / (1.0f + __expf(-(f0.x * f1.x)));
    __stcs(&out_sigma[(long)b * NSAMP + n], sigma);

    __syncthreads();   // sBase ready

    // ---- tiny MLP: geo part only (6 -> 8 relu -> 3 sigmoid) ----
    float h[8];
    #pragma unroll
    for (int j = 0; j < 8; j++) {
        float v = sBase[j];
        v = fmaf(f0.y, sW0g[0][j], v);
        v = fmaf(f0.z, sW0g[1][j], v);
        v = fmaf(f0.w, sW0g[2][j], v);
        v = fmaf(f1.y, sW0g[3][j], v);
        v = fmaf(f1.z, sW0g[4][j], v);
        v = fmaf(f1.w, sW0g[5][j], v);
        h[j] = fmaxf(v, 0.f);
    }
    float col[3];
    #pragma unroll
    for (int c = 0; c < 3; c++) {
        float v = 0.f;
        #pragma unroll
        for (int j = 0; j < 8; j++) v = fmaf(h[j], sW1[j][c], v);
        col[c] = 1.0f / (1.0f + __expf(-v));
    }

    // ---- exclusive product-scan for transmittance T ----
    float sp = 1.0f - sigma;
    #pragma unroll
    for (int o = 1; o < 32; o <<= 1) {
        float v = __shfl_up_sync(0xffffffffu, sp, o);
        if (lane >= o) sp *= v;
    }
    if (lane == 31) sWarpProd[wid] = sp;
    __syncthreads();
    float prefix = 1.0f;
    #pragma unroll
    for (int w = 0; w < 4; w++) if (w < wid) prefix *= sWarpProd[w];
    float excl = __shfl_up_sync(0xffffffffu, sp, 1);
    if (lane == 0) excl = 1.0f;
    const float T = prefix * excl;
    const float wgt = T * sigma;

    // ---- rgb = sum_n wgt * color ----
    float r0 = wgt * col[0], r1 = wgt * col[1], r2 = wgt * col[2];
    #pragma unroll
    for (int o = 16; o > 0; o >>= 1) {
        r0 += __shfl_down_sync(0xffffffffu, r0, o);
        r1 += __shfl_down_sync(0xffffffffu, r1, o);
        r2 += __shfl_down_sync(0xffffffffu, r2, o);
    }
    if (lane == 0) { sRGB[wid][0] = r0; sRGB[wid][1] = r1; sRGB[wid][2] = r2; }
    __syncthreads();
    if (n < 3) {
        out_rgb[b * 3 + n] = sRGB[0][n] + sRGB[1][n] + sRGB[2][n] + sRGB[3][n];
    }
}

extern "C" void kernel_launch(void* const* d_in, const int* in_sizes, int n_in,
                              void* d_out, int out_size) {
    const int2*   x    = (const int2*)d_in[0];
    const float*  dvec = (const float*)d_in[1];
    const float4* grid = (const float4*)d_in[2];
    const float*  W0   = (const float*)d_in[3];
    const float*  W1   = (const float*)d_in[4];

    const int B = in_sizes[1] / 16;          // d is [B, 16]
    float* out_sigma = (float*)d_out;        // [B, 128]
    float* out_rgb   = out_sigma + (long)B * NSAMP;  // [B, 3]

    surf_kernel<<<B, NSAMP>>>(x, dvec, grid, W0, W1, out_sigma, out_rgb);
}